// round 11
// baseline (speedup 1.0000x reference)
#include <cuda_runtime.h>
#include <cuda_fp16.h>
#include <cstdint>
#include <math.h>

// Problem constants
#define Bv    2048
#define Dv    1024
#define Hv    8
#define HDv   128
#define Fv    4096
#define Lv    2
#define Mclip 256
#define MEMv  16
#define Sv    17
#define STOv  1024
#define ACTv  32
#define HIDv  1024
#define NTOK  (Bv*Sv)       // 34816
#define TOKC  (STOv+ACTv)   // 1056
#define TOKCP 1088          // padded to multiple of 64
#define QKVN  3072
#define EPSv  1e-4f
#define SCALEv 0.08838834764831845f  // 128^-0.5

// ---------------- scratch (static device memory; no allocations) -----------
__device__ __half g_tokcat[Bv*TOKCP];
__device__ float  g_hid [Bv*HIDv];
__device__ __half g_hidh[Bv*HIDv];
__device__ float  g_seq [NTOK*Dv];
__device__ __half g_xn  [NTOK*Dv];
__device__ __half g_qkv [(size_t)NTOK*QKVN];
__device__ __half g_att [NTOK*Dv];
__device__ __half g_ff  [(size_t)NTOK*Fv];
// fp16 weights, [N][K] K-major (transposed)
#define W_INP1_OFF  0
#define W_INP2_OFF  (W_INP1_OFF + (size_t)HIDv*TOKCP)
#define W_QKV_OFF   (W_INP2_OFF + (size_t)Dv*HIDv)
#define W_O_OFF     (W_QKV_OFF + (size_t)Lv*QKVN*Dv)
#define W_F1_OFF    (W_O_OFF + (size_t)Lv*Dv*Dv)
#define W_F2_OFF    (W_F1_OFF + (size_t)Lv*Fv*Dv)
#define W_TOTAL     (W_F2_OFF + (size_t)Lv*Dv*Fv)
__device__ __half g_w[W_TOTAL];
__device__ float g_bqkv[Lv*QKVN];

// ---------------- helpers ---------------------------------------------------
__device__ __forceinline__ void mma16(float c[4], const uint32_t a[4], const uint32_t b[2]){
    asm volatile(
        "mma.sync.aligned.m16n8k16.row.col.f32.f16.f16.f32 "
        "{%0,%1,%2,%3}, {%4,%5,%6,%7}, {%8,%9}, {%0,%1,%2,%3};\n"
        : "+f"(c[0]), "+f"(c[1]), "+f"(c[2]), "+f"(c[3])
        : "r"(a[0]), "r"(a[1]), "r"(a[2]), "r"(a[3]), "r"(b[0]), "r"(b[1]));
}

__device__ __forceinline__ void cpa16(uint32_t s, const void* g){
    asm volatile("cp.async.cg.shared.global [%0], [%1], 16;\n" :: "r"(s), "l"(g));
}
#define CP_COMMIT() asm volatile("cp.async.commit_group;\n" ::: "memory")
#define CP_WAIT(n)  asm volatile("cp.async.wait_group %0;\n" :: "n"(n) : "memory")

__device__ __forceinline__ float block_reduce_sum_256(float val){
    __shared__ float sh[8];
    __shared__ float tot;
    int lane = threadIdx.x & 31, wid = threadIdx.x >> 5;
    #pragma unroll
    for (int o = 16; o; o >>= 1) val += __shfl_xor_sync(0xffffffffu, val, o);
    if (lane == 0) sh[wid] = val;
    __syncthreads();
    if (wid == 0){
        float v = (lane < 8) ? sh[lane] : 0.f;
        #pragma unroll
        for (int o = 4; o; o >>= 1) v += __shfl_xor_sync(0xffffffffu, v, o);
        if (lane == 0) tot = v;
    }
    __syncthreads();
    return tot;
}

// ---------------- batched weight convert: [K,N] fp32 -> [N,Kpad] fp16 -------
struct WB9 { const float* src[9]; __half* dst[9]; };

__global__ void wcvt_batch(WB9 wb, int Kin, int Kpad, int N)
{
    __shared__ float t[32][33];
    const float* in = wb.src[blockIdx.z];
    __half* out = wb.dst[blockIdx.z];
    int kb = blockIdx.y * 32, nb = blockIdx.x * 32;
    int tx = threadIdx.x, ty = threadIdx.y;   // block (32,8)
    #pragma unroll
    for (int j = 0; j < 4; j++){
        int k = kb + ty + j*8;
        t[ty + j*8][tx] = (k < Kin) ? in[(size_t)k * N + nb + tx] : 0.f;
    }
    __syncthreads();
    #pragma unroll
    for (int j = 0; j < 4; j++)
        out[(size_t)(nb + ty + j*8) * Kpad + kb + tx] = __float2half_rn(t[tx][ty + j*8]);
}

__global__ void packb_qkv_k(const float* __restrict__ bq, const float* __restrict__ bk,
                            const float* __restrict__ bv, float* __restrict__ out)
{
    int i = blockIdx.x * blockDim.x + threadIdx.x;
    if (i >= Lv * QKVN) return;
    int l = i / QKVN, c = i % QKVN;
    const float* src = (c < Dv) ? bq : (c < 2*Dv) ? bk : bv;
    out[i] = src[l * Dv + (c & (Dv - 1))];
}

// ---------------- fp16 GEMM 128x128 (for N=1024 GEMMs + input MLP) ----------
#define BMh 128
#define BNh 128
#define BKh 64
#define LDAh 72
#define ASZh (BMh*LDAh)
#define STGH (2*ASZh)
#define NSTG 3
#define GEMM_SMEMH (NSTG*STGH*2)   // 110592 B

__global__ void __launch_bounds__(256, 2) gemm_h(
    const __half* __restrict__ A, const __half* __restrict__ Wt,
    const float* __restrict__ bias, const float* __restrict__ res,
    float* __restrict__ C, __half* __restrict__ Ch,
    int M, int N, int K, int lda, int ldc, int act, int outHalf)
{
    extern __shared__ __half smh[];

    const int tid  = threadIdx.x;
    const int lane = tid & 31;
    const int warp = tid >> 5;
    const int wm   = (warp >> 2) * 64;
    const int wn   = (warp & 3) * 32;
    const int bm   = blockIdx.y * BMh;
    const int bn   = blockIdx.x * BNh;
    const int g    = lane >> 2;
    const int tg   = lane & 3;

    float c[4][4][4];
    #pragma unroll
    for (int mi = 0; mi < 4; mi++)
        #pragma unroll
        for (int ni = 0; ni < 4; ni++)
            #pragma unroll
            for (int r = 0; r < 4; r++) c[mi][ni][r] = 0.f;

    const int c_row = tid >> 3;
    const int c_c8  = (tid & 7) * 8;
    const __half* Ag = A  + (size_t)(bm + c_row) * lda + c_c8;
    const __half* Bg = Wt + (size_t)(bn + c_row) * K   + c_c8;

    uint32_t smem_u = (uint32_t)__cvta_generic_to_shared(smh);
    uint32_t aoff[4], boff[4];
    #pragma unroll
    for (int r = 0; r < 4; r++){
        aoff[r] = ((c_row + r*32) * LDAh + c_c8) * 2;
        boff[r] = aoff[r] + ASZh*2;
    }

    const int nk = K / BKh;

    #pragma unroll
    for (int s = 0; s < 2; s++){
        uint32_t sb = smem_u + s * (STGH*2);
        int k0 = s * BKh;
        #pragma unroll
        for (int r = 0; r < 4; r++) cpa16(sb + aoff[r], Ag + (size_t)r*32*lda + k0);
        #pragma unroll
        for (int r = 0; r < 4; r++) cpa16(sb + boff[r], Bg + (size_t)r*32*K + k0);
        CP_COMMIT();
    }

    int s = 0;
    for (int kt = 0; kt < nk; kt++){
        if (kt + 1 < nk) CP_WAIT(1); else CP_WAIT(0);
        __syncthreads();

        int pf = kt + 2;
        if (pf < nk){
            int ps = pf % NSTG;
            uint32_t sb = smem_u + ps * (STGH*2);
            int k0 = pf * BKh;
            #pragma unroll
            for (int r = 0; r < 4; r++) cpa16(sb + aoff[r], Ag + (size_t)r*32*lda + k0);
            #pragma unroll
            for (int r = 0; r < 4; r++) cpa16(sb + boff[r], Bg + (size_t)r*32*K + k0);
            CP_COMMIT();
        }

        const __half* As = smh + s * STGH;
        const __half* Bs = As + ASZh;
        #pragma unroll
        for (int ks = 0; ks < BKh; ks += 16){
            uint32_t a[4][4], b[4][2];
            #pragma unroll
            for (int mi = 0; mi < 4; mi++){
                int rm = wm + mi * 16 + g;
                const __half* p0 = As + rm * LDAh + ks + 2*tg;
                a[mi][0] = *reinterpret_cast<const uint32_t*>(p0);
                a[mi][1] = *reinterpret_cast<const uint32_t*>(p0 + 8*LDAh);
                a[mi][2] = *reinterpret_cast<const uint32_t*>(p0 + 8);
                a[mi][3] = *reinterpret_cast<const uint32_t*>(p0 + 8*LDAh + 8);
            }
            #pragma unroll
            for (int ni = 0; ni < 4; ni++){
                int cn = wn + ni * 8 + g;
                const __half* p0 = Bs + cn * LDAh + ks + 2*tg;
                b[ni][0] = *reinterpret_cast<const uint32_t*>(p0);
                b[ni][1] = *reinterpret_cast<const uint32_t*>(p0 + 8);
            }
            #pragma unroll
            for (int mi = 0; mi < 4; mi++)
                #pragma unroll
                for (int ni = 0; ni < 4; ni++)
                    mma16(c[mi][ni], a[mi], b[ni]);
        }
        s++; if (s == NSTG) s = 0;
    }

    #pragma unroll
    for (int mi = 0; mi < 4; mi++){
        #pragma unroll
        for (int ni = 0; ni < 4; ni++){
            int col = bn + wn + ni * 8 + tg * 2;
            float bx = bias[col], by = bias[col + 1];
            #pragma unroll
            for (int h = 0; h < 2; h++){
                int row = bm + wm + mi * 16 + g + h * 8;
                float v0 = c[mi][ni][h * 2 + 0] + bx;
                float v1 = c[mi][ni][h * 2 + 1] + by;
                if (act == 1){
                    v0 = 0.5f * v0 * (1.0f + erff(v0 * 0.7071067811865475f));
                    v1 = 0.5f * v1 * (1.0f + erff(v1 * 0.7071067811865475f));
                }
                size_t o = (size_t)row * ldc + col;
                if (outHalf){
                    *reinterpret_cast<__half2*>(Ch + o) = __floats2half2_rn(v0, v1);
                } else {
                    if (res){ v0 += res[o]; v1 += res[o + 1]; }
                    *reinterpret_cast<float2*>(C + o) = make_float2(v0, v1);
                }
            }
        }
    }
}

// ---------------- fp16 GEMM 128x256 (QKV / FF1) ------------------------------
// 512 threads, 16 warps (4x4), warp tile 32x64, BK=64h, 3-stage.
#define BM2 128
#define BN2 256
#define BK2 64
#define LD2 72
#define ASZ2 (BM2*LD2)             // 9216 halves
#define BSZ2 (BN2*LD2)             // 18432 halves
#define STG2 (ASZ2+BSZ2)           // 27648 halves
#define NSTG2 3
#define GEMM_SMEM2 (NSTG2*STG2*2)  // 165888 B

__global__ void __launch_bounds__(512, 1) gemm_h2(
    const __half* __restrict__ A, const __half* __restrict__ Wt,
    const float* __restrict__ bias,
    __half* __restrict__ Ch,
    int M, int N, int K, int lda, int ldc, int act)
{
    extern __shared__ __half smh[];

    const int tid  = threadIdx.x;
    const int lane = tid & 31;
    const int warp = tid >> 5;
    const int wm   = (warp >> 2) * 32;     // 0,32,64,96
    const int wn   = (warp & 3) * 64;      // 0,64,128,192
    const int bm   = blockIdx.y * BM2;
    const int bn   = blockIdx.x * BN2;
    const int g    = lane >> 2;
    const int tg   = lane & 3;

    float c[2][8][4];
    #pragma unroll
    for (int mi = 0; mi < 2; mi++)
        #pragma unroll
        for (int ni = 0; ni < 8; ni++)
            #pragma unroll
            for (int r = 0; r < 4; r++) c[mi][ni][r] = 0.f;

    // A: 1024 chunks (2/thread), B: 2048 chunks (4/thread)
    const int a_r0 = tid >> 3;             // 0..63, +64 for j=1
    const int c_c8 = (tid & 7) * 8;
    const __half* Ag = A  + (size_t)(bm + a_r0) * lda + c_c8;
    const __half* Bg = Wt + (size_t)(bn + a_r0) * K   + c_c8;

    uint32_t smem_u = (uint32_t)__cvta_generic_to_shared(smh);
    uint32_t aoff[2], boff[4];
    #pragma unroll
    for (int j = 0; j < 2; j++) aoff[j] = ((a_r0 + j*64) * LD2 + c_c8) * 2;
    #pragma unroll
    for (int j = 0; j < 4; j++) boff[j] = (ASZ2 + (a_r0 + j*64) * LD2 + c_c8) * 2;

    const int nk = K / BK2;

    #pragma unroll
    for (int s = 0; s < 2; s++){
        uint32_t sb = smem_u + s * (STG2*2);
        int k0 = s * BK2;
        #pragma unroll
        for (int j = 0; j < 2; j++) cpa16(sb + aoff[j], Ag + (size_t)j*64*lda + k0);
        #pragma unroll
        for (int j = 0; j < 4; j++) cpa16(sb + boff[j], Bg + (size_t)j*64*K + k0);
        CP_COMMIT();
    }

    int s = 0;
    for (int kt = 0; kt < nk; kt++){
        if (kt + 1 < nk) CP_WAIT(1); else CP_WAIT(0);
        __syncthreads();

        int pf = kt + 2;
        if (pf < nk){
            int ps = pf % NSTG2;
            uint32_t sb = smem_u + ps * (STG2*2);
            int k0 = pf * BK2;
            #pragma unroll
            for (int j = 0; j < 2; j++) cpa16(sb + aoff[j], Ag + (size_t)j*64*lda + k0);
            #pragma unroll
            for (int j = 0; j < 4; j++) cpa16(sb + boff[j], Bg + (size_t)j*64*K + k0);
            CP_COMMIT();
        }

        const __half* As = smh + s * STG2;
        const __half* Bs = As + ASZ2;
        #pragma unroll
        for (int ks = 0; ks < BK2; ks += 16){
            uint32_t a[2][4], b[8][2];
            #pragma unroll
            for (int mi = 0; mi < 2; mi++){
                int rm = wm + mi * 16 + g;
                const __half* p0 = As + rm * LD2 + ks + 2*tg;
                a[mi][0] = *reinterpret_cast<const uint32_t*>(p0);
                a[mi][1] = *reinterpret_cast<const uint32_t*>(p0 + 8*LD2);
                a[mi][2] = *reinterpret_cast<const uint32_t*>(p0 + 8);
                a[mi][3] = *reinterpret_cast<const uint32_t*>(p0 + 8*LD2 + 8);
            }
            #pragma unroll
            for (int ni = 0; ni < 8; ni++){
                int cn = wn + ni * 8 + g;
                const __half* p0 = Bs + cn * LD2 + ks + 2*tg;
                b[ni][0] = *reinterpret_cast<const uint32_t*>(p0);
                b[ni][1] = *reinterpret_cast<const uint32_t*>(p0 + 8);
            }
            #pragma unroll
            for (int mi = 0; mi < 2; mi++)
                #pragma unroll
                for (int ni = 0; ni < 8; ni++)
                    mma16(c[mi][ni], a[mi], b[ni]);
        }
        s++; if (s == NSTG2) s = 0;
    }

    #pragma unroll
    for (int mi = 0; mi < 2; mi++){
        #pragma unroll
        for (int ni = 0; ni < 8; ni++){
            int col = bn + wn + ni * 8 + tg * 2;
            float bx = bias[col], by = bias[col + 1];
            #pragma unroll
            for (int h = 0; h < 2; h++){
                int row = bm + wm + mi * 16 + g + h * 8;
                float v0 = c[mi][ni][h * 2 + 0] + bx;
                float v1 = c[mi][ni][h * 2 + 1] + by;
                if (act == 1){
                    v0 = 0.5f * v0 * (1.0f + erff(v0 * 0.7071067811865475f));
                    v1 = 0.5f * v1 * (1.0f + erff(v1 * 0.7071067811865475f));
                }
                *reinterpret_cast<__half2*>(Ch + (size_t)row * ldc + col) =
                    __floats2half2_rn(v0, v1);
            }
        }
    }
}

// ---------------- rmsnorm (D=1024), fp16 out; silu optional ------------------
__global__ void rmsnorm_h(const float* __restrict__ x, int ldx,
                          const float* __restrict__ w,
                          __half* __restrict__ y, int silu)
{
    int row = blockIdx.x;
    float4 v = reinterpret_cast<const float4*>(x + (size_t)row * ldx)[threadIdx.x];
    float ss = v.x*v.x + v.y*v.y + v.z*v.z + v.w*v.w;
    ss = block_reduce_sum_256(ss);
    float scale = rsqrtf(ss * (1.0f / Dv) + EPSv);
    float4 wv = reinterpret_cast<const float4*>(w)[threadIdx.x];
    v.x *= scale * wv.x; v.y *= scale * wv.y; v.z *= scale * wv.z; v.w *= scale * wv.w;
    if (silu){
        v.x = v.x / (1.0f + expf(-v.x)); v.y = v.y / (1.0f + expf(-v.y));
        v.z = v.z / (1.0f + expf(-v.z)); v.w = v.w / (1.0f + expf(-v.w));
    }
    __half2* yp = reinterpret_cast<__half2*>(y + (size_t)row * Dv) + threadIdx.x * 2;
    yp[0] = __floats2half2_rn(v.x, v.y);
    yp[1] = __floats2half2_rn(v.z, v.w);
}

// final deter: rmsnorm(x + add) -> fp32 out
__global__ void rmsnorm_f(const float* __restrict__ x, int ldx,
                          const float* __restrict__ add,
                          const float* __restrict__ w,
                          float* __restrict__ y)
{
    int row = blockIdx.x;
    float4 v = reinterpret_cast<const float4*>(x + (size_t)row * ldx)[threadIdx.x];
    float4 a = reinterpret_cast<const float4*>(add + (size_t)row * Dv)[threadIdx.x];
    v.x += a.x; v.y += a.y; v.z += a.z; v.w += a.w;
    float ss = v.x*v.x + v.y*v.y + v.z*v.z + v.w*v.w;
    ss = block_reduce_sum_256(ss);
    float scale = rsqrtf(ss * (1.0f / Dv) + EPSv);
    float4 wv = reinterpret_cast<const float4*>(w)[threadIdx.x];
    v.x *= scale * wv.x; v.y *= scale * wv.y; v.z *= scale * wv.z; v.w *= scale * wv.w;
    reinterpret_cast<float4*>(y + (size_t)row * Dv)[threadIdx.x] = v;
}

// ---------------- attention on packed fp16 QKV: one block per (b,h) ---------
__global__ void attn_k(const __half* __restrict__ QKV, const float* __restrict__ rel,
                       __half* __restrict__ O)
{
    __shared__ float qs[Sv][HDv], ks[Sv][HDv], vs[Sv][HDv], sc[Sv][Sv];
    int bh = blockIdx.x;
    int b = bh >> 3, h = bh & 7;
    size_t rowbase = (size_t)b * Sv * QKVN + (size_t)h * HDv;

    for (int e = threadIdx.x; e < Sv * 64; e += 256){
        int sI = e >> 6, d2 = e & 63;
        const __half* p = QKV + rowbase + (size_t)sI * QKVN + d2 * 2;
        float2 q2 = __half22float2(*reinterpret_cast<const __half2*>(p));
        float2 k2 = __half22float2(*reinterpret_cast<const __half2*>(p + Dv));
        float2 v2 = __half22float2(*reinterpret_cast<const __half2*>(p + 2*Dv));
        qs[sI][d2*2] = q2.x; qs[sI][d2*2+1] = q2.y;
        ks[sI][d2*2] = k2.x; ks[sI][d2*2+1] = k2.y;
        vs[sI][d2*2] = v2.x; vs[sI][d2*2+1] = v2.y;
    }
    __syncthreads();

    int lane = threadIdx.x & 31, warp = threadIdx.x >> 5;
    for (int e = warp; e < Sv * Sv; e += 8){
        int i = e / Sv, j = e % Sv;
        float p = 0.f;
        #pragma unroll
        for (int d = lane; d < HDv; d += 32) p += qs[i][d] * ks[j][d];
        #pragma unroll
        for (int o = 16; o; o >>= 1) p += __shfl_xor_sync(0xffffffffu, p, o);
        if (lane == 0){
            int r = i - j + Mclip;
            sc[i][j] = p * SCALEv + rel[r * Hv + h];
        }
    }
    __syncthreads();

    if (threadIdx.x < Sv){
        int i = threadIdx.x;
        float m = -1e30f;
        #pragma unroll
        for (int j = 0; j < Sv; j++) m = fmaxf(m, sc[i][j]);
        float s = 0.f;
        #pragma unroll
        for (int j = 0; j < Sv; j++){ float e_ = expf(sc[i][j] - m); sc[i][j] = e_; s += e_; }
        float inv = 1.0f / s;
        #pragma unroll
        for (int j = 0; j < Sv; j++) sc[i][j] *= inv;
    }
    __syncthreads();

    size_t obase = (size_t)b * Sv * Dv + (size_t)h * HDv;
    for (int e = threadIdx.x; e < Sv * 64; e += 256){
        int i = e >> 6, d2 = e & 63;
        int d = d2 * 2;
        float a0 = 0.f, a1 = 0.f;
        #pragma unroll
        for (int j = 0; j < Sv; j++){
            a0 += sc[i][j] * vs[j][d];
            a1 += sc[i][j] * vs[j][d+1];
        }
        *reinterpret_cast<__half2*>(O + obase + (size_t)i * Dv + d) =
            __floats2half2_rn(a0, a1);
    }
}

// ---------------- small data-movement kernels -------------------------------
__global__ void tokcat_k(const float* __restrict__ stoch, const float* __restrict__ action,
                         __half* __restrict__ out)
{
    int idx = blockIdx.x * blockDim.x + threadIdx.x;
    if (idx >= Bv * TOKCP) return;
    int b = idx / TOKCP, c = idx - b * TOKCP;
    float v;
    if (c < STOv) v = stoch[(size_t)b * STOv + c];
    else if (c < TOKC){ float a = action[(size_t)b * ACTv + (c - STOv)]; v = a / fmaxf(fabsf(a), 1.0f); }
    else v = 0.f;
    out[idx] = __float2half_rn(v);
}

__global__ void mem_in_k(const float* __restrict__ memory, float* __restrict__ seq)
{
    int idx = blockIdx.x * blockDim.x + threadIdx.x;
    if (idx >= Bv * MEMv * Dv / 4) return;
    int b = idx / (MEMv * Dv / 4);
    int r = idx - b * (MEMv * Dv / 4);
    reinterpret_cast<float4*>(seq + (size_t)b * Sv * Dv)[r] =
        reinterpret_cast<const float4*>(memory)[idx];
}

__global__ void mem_out_k(const float* __restrict__ seq, float* __restrict__ out)
{
    int idx = blockIdx.x * blockDim.x + threadIdx.x;
    if (idx >= Bv * MEMv * Dv / 4) return;
    int b = idx / (MEMv * Dv / 4);
    reinterpret_cast<float4*>(out)[idx] =
        reinterpret_cast<const float4*>(seq + (size_t)(b + 1) * Dv)[idx];  // seq[:,1:17,:]
}

// ---------------- driver ----------------------------------------------------
extern "C" void kernel_launch(void* const* d_in, const int* in_sizes, int n_in,
                              void* d_out, int out_size)
{
    (void)in_sizes; (void)n_in; (void)out_size;
    const float* stoch   = (const float*)d_in[0];
    const float* deter   = (const float*)d_in[1];
    const float* action  = (const float*)d_in[2];
    const float* memory  = (const float*)d_in[3];
    const float* inp_w1  = (const float*)d_in[4];
    const float* inp_b1  = (const float*)d_in[5];
    const float* inp_nw  = (const float*)d_in[6];
    const float* inp_w2  = (const float*)d_in[7];
    const float* inp_b2  = (const float*)d_in[8];
    const float* Wq      = (const float*)d_in[9];
    const float* bq      = (const float*)d_in[10];
    const float* Wk      = (const float*)d_in[11];
    const float* bk      = (const float*)d_in[12];
    const float* Wv      = (const float*)d_in[13];
    const float* bv      = (const float*)d_in[14];
    const float* Wo      = (const float*)d_in[15];
    const float* bo      = (const float*)d_in[16];
    const float* rel_emb = (const float*)d_in[17];
    const float* n1w     = (const float*)d_in[18];
    const float* n2w     = (const float*)d_in[19];
    const float* ffw1    = (const float*)d_in[20];
    const float* ffb1    = (const float*)d_in[21];
    const float* ffw2    = (const float*)d_in[22];
    const float* ffb2    = (const float*)d_in[23];
    const float* fnw     = (const float*)d_in[24];
    float* out = (float*)d_out;

    __half *p_tokcat, *p_hidh, *p_xn, *p_qkv, *p_att, *p_ff, *p_w;
    float *p_hid, *p_seq, *p_bqkv;
    cudaGetSymbolAddress((void**)&p_tokcat, g_tokcat);
    cudaGetSymbolAddress((void**)&p_hid,  g_hid);
    cudaGetSymbolAddress((void**)&p_hidh, g_hidh);
    cudaGetSymbolAddress((void**)&p_seq,  g_seq);
    cudaGetSymbolAddress((void**)&p_xn,   g_xn);
    cudaGetSymbolAddress((void**)&p_qkv,  g_qkv);
    cudaGetSymbolAddress((void**)&p_att,  g_att);
    cudaGetSymbolAddress((void**)&p_ff,   g_ff);
    cudaGetSymbolAddress((void**)&p_w,    g_w);
    cudaGetSymbolAddress((void**)&p_bqkv, g_bqkv);

    cudaFuncSetAttribute(gemm_h,  cudaFuncAttributeMaxDynamicSharedMemorySize, GEMM_SMEMH);
    cudaFuncSetAttribute(gemm_h2, cudaFuncAttributeMaxDynamicSharedMemorySize, GEMM_SMEM2);

    __half* w_inp1 = p_w + W_INP1_OFF;
    __half* w_inp2 = p_w + W_INP2_OFF;
    __half* w_qkv  = p_w + W_QKV_OFF;
    __half* w_o    = p_w + W_O_OFF;
    __half* w_f1   = p_w + W_F1_OFF;
    __half* w_f2   = p_w + W_F2_OFF;

    // ---- batched weight convert/transpose to fp16 [N][Kpad] ----
    {
        // group 1: shape (Kin=1024, Kpad=1024, N=1024): Wq,Wk,Wv,Wo x2 + inp_w2 (9)
        WB9 wb1{};
        for (int l = 0; l < Lv; l++){
            __half* dq = w_qkv + (size_t)l*QKVN*Dv;
            wb1.src[l*4+0] = Wq + (size_t)l*Dv*Dv; wb1.dst[l*4+0] = dq;
            wb1.src[l*4+1] = Wk + (size_t)l*Dv*Dv; wb1.dst[l*4+1] = dq + (size_t)Dv*Dv;
            wb1.src[l*4+2] = Wv + (size_t)l*Dv*Dv; wb1.dst[l*4+2] = dq + (size_t)2*Dv*Dv;
            wb1.src[l*4+3] = Wo + (size_t)l*Dv*Dv; wb1.dst[l*4+3] = w_o + (size_t)l*Dv*Dv;
        }
        wb1.src[8] = inp_w2; wb1.dst[8] = w_inp2;
        wcvt_batch<<<dim3(Dv/32, Dv/32, 9), dim3(32,8)>>>(wb1, Dv, Dv, Dv);

        // group 2: ffw1 x2, shape (1024,1024,4096)
        WB9 wb2{};
        for (int l = 0; l < Lv; l++){
            wb2.src[l] = ffw1 + (size_t)l*Dv*Fv; wb2.dst[l] = w_f1 + (size_t)l*Fv*Dv;
        }
        wcvt_batch<<<dim3(Fv/32, Dv/32, 2), dim3(32,8)>>>(wb2, Dv, Dv, Fv);

        // group 3: ffw2 x2, shape (4096,4096,1024)
        WB9 wb3{};
        for (int l = 0; l < Lv; l++){
            wb3.src[l] = ffw2 + (size_t)l*Fv*Dv; wb3.dst[l] = w_f2 + (size_t)l*Dv*Fv;
        }
        wcvt_batch<<<dim3(Dv/32, Fv/32, 2), dim3(32,8)>>>(wb3, Fv, Fv, Dv);

        // group 4: inp_w1 (1056->1088 pad, N=1024)
        WB9 wb4{};
        wb4.src[0] = inp_w1; wb4.dst[0] = w_inp1;
        wcvt_batch<<<dim3(HIDv/32, TOKCP/32, 1), dim3(32,8)>>>(wb4, TOKC, TOKCP, HIDv);
    }
    packb_qkv_k<<<(Lv * QKVN + 255) / 256, 256>>>(bq, bk, bv, p_bqkv);

    // prep
    tokcat_k<<<(Bv * TOKCP + 255) / 256, 256>>>(stoch, action, p_tokcat);
    mem_in_k<<<(Bv * MEMv * Dv / 4 + 255) / 256, 256>>>(memory, p_seq);

    // input MLP
    dim3 gI(HIDv / BNh, Bv / BMh);         // 8 x 16
    gemm_h<<<gI, 256, GEMM_SMEMH>>>(p_tokcat, w_inp1, inp_b1, nullptr, p_hid, nullptr,
                                    Bv, HIDv, TOKCP, TOKCP, HIDv, 0, 0);
    rmsnorm_h<<<Bv, 256>>>(p_hid, Dv, inp_nw, p_hidh, 1);
    gemm_h<<<gI, 256, GEMM_SMEMH>>>(p_hidh, w_inp2, inp_b2, nullptr,
                                    p_seq + (size_t)MEMv * Dv, nullptr,
                                    Bv, Dv, HIDv, HIDv, Sv * Dv, 0, 0);

    dim3 gQ2(QKVN / BN2, NTOK / BM2);      // 12 x 272
    dim3 gP(Dv / BNh, NTOK / BMh);         // 8 x 272
    dim3 gF2(Fv / BN2, NTOK / BM2);        // 16 x 272

    for (int l = 0; l < Lv; l++){
        const __half* wqkv = w_qkv + (size_t)l * QKVN * Dv;
        const __half* wo   = w_o   + (size_t)l * Dv * Dv;
        const __half* f1   = w_f1  + (size_t)l * Fv * Dv;
        const __half* f2   = w_f2  + (size_t)l * Dv * Fv;

        rmsnorm_h<<<NTOK, 256>>>(p_seq, Dv, n1w + l * Dv, p_xn, 0);
        gemm_h2<<<gQ2, 512, GEMM_SMEM2>>>(p_xn, wqkv, p_bqkv + l * QKVN, p_qkv,
                                          NTOK, QKVN, Dv, Dv, QKVN, 0);
        attn_k<<<Bv * Hv, 256>>>(p_qkv, rel_emb + (size_t)l * (2 * Mclip + 1) * Hv, p_att);
        gemm_h<<<gP, 256, GEMM_SMEMH>>>(p_att, wo, bo + l * Dv, p_seq,
                                        p_seq, nullptr, NTOK, Dv, Dv, Dv, Dv, 0, 0);
        rmsnorm_h<<<NTOK, 256>>>(p_seq, Dv, n2w + l * Dv, p_xn, 0);
        gemm_h2<<<gF2, 512, GEMM_SMEM2>>>(p_xn, f1, ffb1 + l * Fv, p_ff,
                                          NTOK, Fv, Dv, Dv, Fv, 1);
        gemm_h<<<gP, 256, GEMM_SMEMH>>>(p_ff, f2, ffb2 + l * Dv, p_seq,
                                        p_seq, nullptr, NTOK, Dv, Fv, Fv, Dv, 0, 0);
    }

    // new_deter = rmsnorm(seq[:, -1] + deter, fnw)  -> out[0 : B*D)
    rmsnorm_f<<<Bv, 256>>>(p_seq + (size_t)MEMv * Dv, Sv * Dv, deter, fnw, out);
    // new_mem = seq[:, 1:17]  -> out[B*D : ]
    mem_out_k<<<(Bv * MEMv * Dv / 4 + 255) / 256, 256>>>(p_seq, out + (size_t)Bv * Dv);
}

// round 12
// speedup vs baseline: 1.0876x; 1.0876x over previous
#include <cuda_runtime.h>
#include <cuda_fp16.h>
#include <cstdint>
#include <math.h>

// Problem constants
#define Bv    2048
#define Dv    1024
#define Hv    8
#define HDv   128
#define Fv    4096
#define Lv    2
#define Mclip 256
#define MEMv  16
#define Sv    17
#define STOv  1024
#define ACTv  32
#define HIDv  1024
#define NTOK  (Bv*Sv)       // 34816
#define TOKC  (STOv+ACTv)   // 1056
#define TOKCP 1088          // padded to multiple of 64
#define QKVN  3072
#define EPSv  1e-4f
#define SCALEv 0.08838834764831845f  // 128^-0.5

// ---------------- scratch (static device memory; no allocations) -----------
__device__ __half g_tokcat[Bv*TOKCP];
__device__ float  g_hid [Bv*HIDv];
__device__ __half g_hidh[Bv*HIDv];
__device__ float  g_seq [NTOK*Dv];
__device__ __half g_xn  [NTOK*Dv];
__device__ __half g_qkv [(size_t)NTOK*QKVN];
__device__ __half g_att [NTOK*Dv];
__device__ __half g_ff  [(size_t)NTOK*Fv];
// fp16 weights, [N][K] K-major (transposed)
#define W_INP1_OFF  0
#define W_INP2_OFF  (W_INP1_OFF + (size_t)HIDv*TOKCP)
#define W_QKV_OFF   (W_INP2_OFF + (size_t)Dv*HIDv)
#define W_O_OFF     (W_QKV_OFF + (size_t)Lv*QKVN*Dv)
#define W_F1_OFF    (W_O_OFF + (size_t)Lv*Dv*Dv)
#define W_F2_OFF    (W_F1_OFF + (size_t)Lv*Fv*Dv)
#define W_TOTAL     (W_F2_OFF + (size_t)Lv*Dv*Fv)
__device__ __half g_w[W_TOTAL];
__device__ float g_bqkv[Lv*QKVN];

// ---------------- helpers ---------------------------------------------------
__device__ __forceinline__ void mma16(float c[4], const uint32_t a[4], const uint32_t b[2]){
    asm volatile(
        "mma.sync.aligned.m16n8k16.row.col.f32.f16.f16.f32 "
        "{%0,%1,%2,%3}, {%4,%5,%6,%7}, {%8,%9}, {%0,%1,%2,%3};\n"
        : "+f"(c[0]), "+f"(c[1]), "+f"(c[2]), "+f"(c[3])
        : "r"(a[0]), "r"(a[1]), "r"(a[2]), "r"(a[3]), "r"(b[0]), "r"(b[1]));
}

__device__ __forceinline__ void cpa16(uint32_t s, const void* g){
    asm volatile("cp.async.cg.shared.global [%0], [%1], 16;\n" :: "r"(s), "l"(g));
}
#define CP_COMMIT() asm volatile("cp.async.commit_group;\n" ::: "memory")
#define CP_WAIT(n)  asm volatile("cp.async.wait_group %0;\n" :: "n"(n) : "memory")

__device__ __forceinline__ float block_reduce_sum_256(float val){
    __shared__ float sh[8];
    __shared__ float tot;
    int lane = threadIdx.x & 31, wid = threadIdx.x >> 5;
    #pragma unroll
    for (int o = 16; o; o >>= 1) val += __shfl_xor_sync(0xffffffffu, val, o);
    if (lane == 0) sh[wid] = val;
    __syncthreads();
    if (wid == 0){
        float v = (lane < 8) ? sh[lane] : 0.f;
        #pragma unroll
        for (int o = 4; o; o >>= 1) v += __shfl_xor_sync(0xffffffffu, v, o);
        if (lane == 0) tot = v;
    }
    __syncthreads();
    return tot;
}

// ---------------- batched weight convert: [K,N] fp32 -> [N,Kpad] fp16 -------
struct WB9 { const float* src[9]; __half* dst[9]; };

__global__ void wcvt_batch(WB9 wb, int Kin, int Kpad, int N)
{
    __shared__ float t[32][33];
    const float* in = wb.src[blockIdx.z];
    __half* out = wb.dst[blockIdx.z];
    int kb = blockIdx.y * 32, nb = blockIdx.x * 32;
    int tx = threadIdx.x, ty = threadIdx.y;   // block (32,8)
    #pragma unroll
    for (int j = 0; j < 4; j++){
        int k = kb + ty + j*8;
        t[ty + j*8][tx] = (k < Kin) ? in[(size_t)k * N + nb + tx] : 0.f;
    }
    __syncthreads();
    #pragma unroll
    for (int j = 0; j < 4; j++)
        out[(size_t)(nb + ty + j*8) * Kpad + kb + tx] = __float2half_rn(t[tx][ty + j*8]);
}

__global__ void packb_qkv_k(const float* __restrict__ bq, const float* __restrict__ bk,
                            const float* __restrict__ bv, float* __restrict__ out)
{
    int i = blockIdx.x * blockDim.x + threadIdx.x;
    if (i >= Lv * QKVN) return;
    int l = i / QKVN, c = i % QKVN;
    const float* src = (c < Dv) ? bq : (c < 2*Dv) ? bk : bv;
    out[i] = src[l * Dv + (c & (Dv - 1))];
}

// ---------------- fp16 GEMM 128x128, 256 thr, 3-stage, 2 CTA/SM -------------
#define BMh 128
#define BNh 128
#define BKh 64
#define LDAh 72
#define ASZh (BMh*LDAh)
#define STGH (2*ASZh)
#define NSTG 3
#define GEMM_SMEMH (NSTG*STGH*2)   // 110592 B

__global__ void __launch_bounds__(256, 2) gemm_h(
    const __half* __restrict__ A, const __half* __restrict__ Wt,
    const float* __restrict__ bias, const float* __restrict__ res,
    float* __restrict__ C, __half* __restrict__ Ch,
    int M, int N, int K, int lda, int ldc, int act, int outHalf)
{
    extern __shared__ __half smh[];

    const int tid  = threadIdx.x;
    const int lane = tid & 31;
    const int warp = tid >> 5;
    const int wm   = (warp >> 2) * 64;
    const int wn   = (warp & 3) * 32;
    const int bm   = blockIdx.y * BMh;
    const int bn   = blockIdx.x * BNh;
    const int g    = lane >> 2;
    const int tg   = lane & 3;

    float c[4][4][4];
    #pragma unroll
    for (int mi = 0; mi < 4; mi++)
        #pragma unroll
        for (int ni = 0; ni < 4; ni++)
            #pragma unroll
            for (int r = 0; r < 4; r++) c[mi][ni][r] = 0.f;

    const int c_row = tid >> 3;
    const int c_c8  = (tid & 7) * 8;
    const __half* Ag = A  + (size_t)(bm + c_row) * lda + c_c8;
    const __half* Bg = Wt + (size_t)(bn + c_row) * K   + c_c8;

    uint32_t smem_u = (uint32_t)__cvta_generic_to_shared(smh);
    uint32_t aoff[4], boff[4];
    #pragma unroll
    for (int r = 0; r < 4; r++){
        aoff[r] = ((c_row + r*32) * LDAh + c_c8) * 2;
        boff[r] = aoff[r] + ASZh*2;
    }

    const int nk = K / BKh;

    #pragma unroll
    for (int s = 0; s < 2; s++){
        uint32_t sb = smem_u + s * (STGH*2);
        int k0 = s * BKh;
        #pragma unroll
        for (int r = 0; r < 4; r++) cpa16(sb + aoff[r], Ag + (size_t)r*32*lda + k0);
        #pragma unroll
        for (int r = 0; r < 4; r++) cpa16(sb + boff[r], Bg + (size_t)r*32*K + k0);
        CP_COMMIT();
    }

    int s = 0;
    for (int kt = 0; kt < nk; kt++){
        if (kt + 1 < nk) CP_WAIT(1); else CP_WAIT(0);
        __syncthreads();

        int pf = kt + 2;
        if (pf < nk){
            int ps = pf % NSTG;
            uint32_t sb = smem_u + ps * (STGH*2);
            int k0 = pf * BKh;
            #pragma unroll
            for (int r = 0; r < 4; r++) cpa16(sb + aoff[r], Ag + (size_t)r*32*lda + k0);
            #pragma unroll
            for (int r = 0; r < 4; r++) cpa16(sb + boff[r], Bg + (size_t)r*32*K + k0);
            CP_COMMIT();
        }

        const __half* As = smh + s * STGH;
        const __half* Bs = As + ASZh;
        #pragma unroll
        for (int ks = 0; ks < BKh; ks += 16){
            uint32_t a[4][4], b[4][2];
            #pragma unroll
            for (int mi = 0; mi < 4; mi++){
                int rm = wm + mi * 16 + g;
                const __half* p0 = As + rm * LDAh + ks + 2*tg;
                a[mi][0] = *reinterpret_cast<const uint32_t*>(p0);
                a[mi][1] = *reinterpret_cast<const uint32_t*>(p0 + 8*LDAh);
                a[mi][2] = *reinterpret_cast<const uint32_t*>(p0 + 8);
                a[mi][3] = *reinterpret_cast<const uint32_t*>(p0 + 8*LDAh + 8);
            }
            #pragma unroll
            for (int ni = 0; ni < 4; ni++){
                int cn = wn + ni * 8 + g;
                const __half* p0 = Bs + cn * LDAh + ks + 2*tg;
                b[ni][0] = *reinterpret_cast<const uint32_t*>(p0);
                b[ni][1] = *reinterpret_cast<const uint32_t*>(p0 + 8);
            }
            #pragma unroll
            for (int mi = 0; mi < 4; mi++)
                #pragma unroll
                for (int ni = 0; ni < 4; ni++)
                    mma16(c[mi][ni], a[mi], b[ni]);
        }
        s++; if (s == NSTG) s = 0;
    }

    #pragma unroll
    for (int mi = 0; mi < 4; mi++){
        #pragma unroll
        for (int ni = 0; ni < 4; ni++){
            int col = bn + wn + ni * 8 + tg * 2;
            float bx = bias[col], by = bias[col + 1];
            #pragma unroll
            for (int h = 0; h < 2; h++){
                int row = bm + wm + mi * 16 + g + h * 8;
                float v0 = c[mi][ni][h * 2 + 0] + bx;
                float v1 = c[mi][ni][h * 2 + 1] + by;
                if (act == 1){
                    v0 = 0.5f * v0 * (1.0f + erff(v0 * 0.7071067811865475f));
                    v1 = 0.5f * v1 * (1.0f + erff(v1 * 0.7071067811865475f));
                }
                size_t o = (size_t)row * ldc + col;
                if (outHalf){
                    *reinterpret_cast<__half2*>(Ch + o) = __floats2half2_rn(v0, v1);
                } else {
                    if (res){ v0 += res[o]; v1 += res[o + 1]; }
                    *reinterpret_cast<float2*>(C + o) = make_float2(v0, v1);
                }
            }
        }
    }
}

// ---------------- rmsnorm (D=1024), fp16 out; silu optional ------------------
__global__ void rmsnorm_h(const float* __restrict__ x, int ldx,
                          const float* __restrict__ w,
                          __half* __restrict__ y, int silu)
{
    int row = blockIdx.x;
    float4 v = reinterpret_cast<const float4*>(x + (size_t)row * ldx)[threadIdx.x];
    float ss = v.x*v.x + v.y*v.y + v.z*v.z + v.w*v.w;
    ss = block_reduce_sum_256(ss);
    float scale = rsqrtf(ss * (1.0f / Dv) + EPSv);
    float4 wv = reinterpret_cast<const float4*>(w)[threadIdx.x];
    v.x *= scale * wv.x; v.y *= scale * wv.y; v.z *= scale * wv.z; v.w *= scale * wv.w;
    if (silu){
        v.x = v.x / (1.0f + expf(-v.x)); v.y = v.y / (1.0f + expf(-v.y));
        v.z = v.z / (1.0f + expf(-v.z)); v.w = v.w / (1.0f + expf(-v.w));
    }
    __half2* yp = reinterpret_cast<__half2*>(y + (size_t)row * Dv) + threadIdx.x * 2;
    yp[0] = __floats2half2_rn(v.x, v.y);
    yp[1] = __floats2half2_rn(v.z, v.w);
}

// final deter: rmsnorm(x + add) -> fp32 out
__global__ void rmsnorm_f(const float* __restrict__ x, int ldx,
                          const float* __restrict__ add,
                          const float* __restrict__ w,
                          float* __restrict__ y)
{
    int row = blockIdx.x;
    float4 v = reinterpret_cast<const float4*>(x + (size_t)row * ldx)[threadIdx.x];
    float4 a = reinterpret_cast<const float4*>(add + (size_t)row * Dv)[threadIdx.x];
    v.x += a.x; v.y += a.y; v.z += a.z; v.w += a.w;
    float ss = v.x*v.x + v.y*v.y + v.z*v.z + v.w*v.w;
    ss = block_reduce_sum_256(ss);
    float scale = rsqrtf(ss * (1.0f / Dv) + EPSv);
    float4 wv = reinterpret_cast<const float4*>(w)[threadIdx.x];
    v.x *= scale * wv.x; v.y *= scale * wv.y; v.z *= scale * wv.z; v.w *= scale * wv.w;
    reinterpret_cast<float4*>(y + (size_t)row * Dv)[threadIdx.x] = v;
}

// ---------------- attention on packed fp16 QKV: one block per (b,h) ---------
__global__ void attn_k(const __half* __restrict__ QKV, const float* __restrict__ rel,
                       __half* __restrict__ O)
{
    __shared__ float qs[Sv][HDv], ks[Sv][HDv], vs[Sv][HDv], sc[Sv][Sv];
    int bh = blockIdx.x;
    int b = bh >> 3, h = bh & 7;
    size_t rowbase = (size_t)b * Sv * QKVN + (size_t)h * HDv;

    for (int e = threadIdx.x; e < Sv * 64; e += 256){
        int sI = e >> 6, d2 = e & 63;
        const __half* p = QKV + rowbase + (size_t)sI * QKVN + d2 * 2;
        float2 q2 = __half22float2(*reinterpret_cast<const __half2*>(p));
        float2 k2 = __half22float2(*reinterpret_cast<const __half2*>(p + Dv));
        float2 v2 = __half22float2(*reinterpret_cast<const __half2*>(p + 2*Dv));
        qs[sI][d2*2] = q2.x; qs[sI][d2*2+1] = q2.y;
        ks[sI][d2*2] = k2.x; ks[sI][d2*2+1] = k2.y;
        vs[sI][d2*2] = v2.x; vs[sI][d2*2+1] = v2.y;
    }
    __syncthreads();

    int lane = threadIdx.x & 31, warp = threadIdx.x >> 5;
    for (int e = warp; e < Sv * Sv; e += 8){
        int i = e / Sv, j = e % Sv;
        float p = 0.f;
        #pragma unroll
        for (int d = lane; d < HDv; d += 32) p += qs[i][d] * ks[j][d];
        #pragma unroll
        for (int o = 16; o; o >>= 1) p += __shfl_xor_sync(0xffffffffu, p, o);
        if (lane == 0){
            int r = i - j + Mclip;
            sc[i][j] = p * SCALEv + rel[r * Hv + h];
        }
    }
    __syncthreads();

    if (threadIdx.x < Sv){
        int i = threadIdx.x;
        float m = -1e30f;
        #pragma unroll
        for (int j = 0; j < Sv; j++) m = fmaxf(m, sc[i][j]);
        float s = 0.f;
        #pragma unroll
        for (int j = 0; j < Sv; j++){ float e_ = expf(sc[i][j] - m); sc[i][j] = e_; s += e_; }
        float inv = 1.0f / s;
        #pragma unroll
        for (int j = 0; j < Sv; j++) sc[i][j] *= inv;
    }
    __syncthreads();

    size_t obase = (size_t)b * Sv * Dv + (size_t)h * HDv;
    for (int e = threadIdx.x; e < Sv * 64; e += 256){
        int i = e >> 6, d2 = e & 63;
        int d = d2 * 2;
        float a0 = 0.f, a1 = 0.f;
        #pragma unroll
        for (int j = 0; j < Sv; j++){
            a0 += sc[i][j] * vs[j][d];
            a1 += sc[i][j] * vs[j][d+1];
        }
        *reinterpret_cast<__half2*>(O + obase + (size_t)i * Dv + d) =
            __floats2half2_rn(a0, a1);
    }
}

// ---------------- small data-movement kernels -------------------------------
__global__ void tokcat_k(const float* __restrict__ stoch, const float* __restrict__ action,
                         __half* __restrict__ out)
{
    int idx = blockIdx.x * blockDim.x + threadIdx.x;
    if (idx >= Bv * TOKCP) return;
    int b = idx / TOKCP, c = idx - b * TOKCP;
    float v;
    if (c < STOv) v = stoch[(size_t)b * STOv + c];
    else if (c < TOKC){ float a = action[(size_t)b * ACTv + (c - STOv)]; v = a / fmaxf(fabsf(a), 1.0f); }
    else v = 0.f;
    out[idx] = __float2half_rn(v);
}

__global__ void mem_in_k(const float* __restrict__ memory, float* __restrict__ seq)
{
    int idx = blockIdx.x * blockDim.x + threadIdx.x;
    if (idx >= Bv * MEMv * Dv / 4) return;
    int b = idx / (MEMv * Dv / 4);
    int r = idx - b * (MEMv * Dv / 4);
    reinterpret_cast<float4*>(seq + (size_t)b * Sv * Dv)[r] =
        reinterpret_cast<const float4*>(memory)[idx];
}

__global__ void mem_out_k(const float* __restrict__ seq, float* __restrict__ out)
{
    int idx = blockIdx.x * blockDim.x + threadIdx.x;
    if (idx >= Bv * MEMv * Dv / 4) return;
    int b = idx / (MEMv * Dv / 4);
    reinterpret_cast<float4*>(out)[idx] =
        reinterpret_cast<const float4*>(seq + (size_t)(b + 1) * Dv)[idx];  // seq[:,1:17,:]
}

// ---------------- driver ----------------------------------------------------
extern "C" void kernel_launch(void* const* d_in, const int* in_sizes, int n_in,
                              void* d_out, int out_size)
{
    (void)in_sizes; (void)n_in; (void)out_size;
    const float* stoch   = (const float*)d_in[0];
    const float* deter   = (const float*)d_in[1];
    const float* action  = (const float*)d_in[2];
    const float* memory  = (const float*)d_in[3];
    const float* inp_w1  = (const float*)d_in[4];
    const float* inp_b1  = (const float*)d_in[5];
    const float* inp_nw  = (const float*)d_in[6];
    const float* inp_w2  = (const float*)d_in[7];
    const float* inp_b2  = (const float*)d_in[8];
    const float* Wq      = (const float*)d_in[9];
    const float* bq      = (const float*)d_in[10];
    const float* Wk      = (const float*)d_in[11];
    const float* bk      = (const float*)d_in[12];
    const float* Wv      = (const float*)d_in[13];
    const float* bv      = (const float*)d_in[14];
    const float* Wo      = (const float*)d_in[15];
    const float* bo      = (const float*)d_in[16];
    const float* rel_emb = (const float*)d_in[17];
    const float* n1w     = (const float*)d_in[18];
    const float* n2w     = (const float*)d_in[19];
    const float* ffw1    = (const float*)d_in[20];
    const float* ffb1    = (const float*)d_in[21];
    const float* ffw2    = (const float*)d_in[22];
    const float* ffb2    = (const float*)d_in[23];
    const float* fnw     = (const float*)d_in[24];
    float* out = (float*)d_out;

    __half *p_tokcat, *p_hidh, *p_xn, *p_qkv, *p_att, *p_ff, *p_w;
    float *p_hid, *p_seq, *p_bqkv;
    cudaGetSymbolAddress((void**)&p_tokcat, g_tokcat);
    cudaGetSymbolAddress((void**)&p_hid,  g_hid);
    cudaGetSymbolAddress((void**)&p_hidh, g_hidh);
    cudaGetSymbolAddress((void**)&p_seq,  g_seq);
    cudaGetSymbolAddress((void**)&p_xn,   g_xn);
    cudaGetSymbolAddress((void**)&p_qkv,  g_qkv);
    cudaGetSymbolAddress((void**)&p_att,  g_att);
    cudaGetSymbolAddress((void**)&p_ff,   g_ff);
    cudaGetSymbolAddress((void**)&p_w,    g_w);
    cudaGetSymbolAddress((void**)&p_bqkv, g_bqkv);

    cudaFuncSetAttribute(gemm_h, cudaFuncAttributeMaxDynamicSharedMemorySize, GEMM_SMEMH);

    __half* w_inp1 = p_w + W_INP1_OFF;
    __half* w_inp2 = p_w + W_INP2_OFF;
    __half* w_qkv  = p_w + W_QKV_OFF;
    __half* w_o    = p_w + W_O_OFF;
    __half* w_f1   = p_w + W_F1_OFF;
    __half* w_f2   = p_w + W_F2_OFF;

    // ---- batched weight convert/transpose to fp16 [N][Kpad] ----
    {
        // group 1: (Kin=1024, Kpad=1024, N=1024): Wq,Wk,Wv,Wo x2 + inp_w2 (9)
        WB9 wb1{};
        for (int l = 0; l < Lv; l++){
            __half* dq = w_qkv + (size_t)l*QKVN*Dv;
            wb1.src[l*4+0] = Wq + (size_t)l*Dv*Dv; wb1.dst[l*4+0] = dq;
            wb1.src[l*4+1] = Wk + (size_t)l*Dv*Dv; wb1.dst[l*4+1] = dq + (size_t)Dv*Dv;
            wb1.src[l*4+2] = Wv + (size_t)l*Dv*Dv; wb1.dst[l*4+2] = dq + (size_t)2*Dv*Dv;
            wb1.src[l*4+3] = Wo + (size_t)l*Dv*Dv; wb1.dst[l*4+3] = w_o + (size_t)l*Dv*Dv;
        }
        wb1.src[8] = inp_w2; wb1.dst[8] = w_inp2;
        wcvt_batch<<<dim3(Dv/32, Dv/32, 9), dim3(32,8)>>>(wb1, Dv, Dv, Dv);

        // group 2: ffw1 x2 (1024 -> N=4096)
        WB9 wb2{};
        for (int l = 0; l < Lv; l++){
            wb2.src[l] = ffw1 + (size_t)l*Dv*Fv; wb2.dst[l] = w_f1 + (size_t)l*Fv*Dv;
        }
        wcvt_batch<<<dim3(Fv/32, Dv/32, 2), dim3(32,8)>>>(wb2, Dv, Dv, Fv);

        // group 3: ffw2 x2 (4096 -> N=1024)
        WB9 wb3{};
        for (int l = 0; l < Lv; l++){
            wb3.src[l] = ffw2 + (size_t)l*Fv*Dv; wb3.dst[l] = w_f2 + (size_t)l*Dv*Fv;
        }
        wcvt_batch<<<dim3(Dv/32, Fv/32, 2), dim3(32,8)>>>(wb3, Fv, Fv, Dv);

        // group 4: inp_w1 (1056 -> 1088 pad, N=1024)
        WB9 wb4{};
        wb4.src[0] = inp_w1; wb4.dst[0] = w_inp1;
        wcvt_batch<<<dim3(HIDv/32, TOKCP/32, 1), dim3(32,8)>>>(wb4, TOKC, TOKCP, HIDv);
    }
    packb_qkv_k<<<(Lv * QKVN + 255) / 256, 256>>>(bq, bk, bv, p_bqkv);

    // prep
    tokcat_k<<<(Bv * TOKCP + 255) / 256, 256>>>(stoch, action, p_tokcat);
    mem_in_k<<<(Bv * MEMv * Dv / 4 + 255) / 256, 256>>>(memory, p_seq);

    // input MLP
    dim3 gI(HIDv / BNh, Bv / BMh);         // 8 x 16
    gemm_h<<<gI, 256, GEMM_SMEMH>>>(p_tokcat, w_inp1, inp_b1, nullptr, p_hid, nullptr,
                                    Bv, HIDv, TOKCP, TOKCP, HIDv, 0, 0);
    rmsnorm_h<<<Bv, 256>>>(p_hid, Dv, inp_nw, p_hidh, 1);
    gemm_h<<<gI, 256, GEMM_SMEMH>>>(p_hidh, w_inp2, inp_b2, nullptr,
                                    p_seq + (size_t)MEMv * Dv, nullptr,
                                    Bv, Dv, HIDv, HIDv, Sv * Dv, 0, 0);

    dim3 gQ(QKVN / BNh, NTOK / BMh);       // 24 x 272
    dim3 gP(Dv / BNh, NTOK / BMh);         // 8 x 272
    dim3 gF(Fv / BNh, NTOK / BMh);         // 32 x 272

    for (int l = 0; l < Lv; l++){
        const __half* wqkv = w_qkv + (size_t)l * QKVN * Dv;
        const __half* wo   = w_o   + (size_t)l * Dv * Dv;
        const __half* f1   = w_f1  + (size_t)l * Fv * Dv;
        const __half* f2   = w_f2  + (size_t)l * Dv * Fv;

        rmsnorm_h<<<NTOK, 256>>>(p_seq, Dv, n1w + l * Dv, p_xn, 0);
        gemm_h<<<gQ, 256, GEMM_SMEMH>>>(p_xn, wqkv, p_bqkv + l * QKVN, nullptr,
                                        nullptr, p_qkv, NTOK, QKVN, Dv, Dv, QKVN, 0, 1);
        attn_k<<<Bv * Hv, 256>>>(p_qkv, rel_emb + (size_t)l * (2 * Mclip + 1) * Hv, p_att);
        gemm_h<<<gP, 256, GEMM_SMEMH>>>(p_att, wo, bo + l * Dv, p_seq,
                                        p_seq, nullptr, NTOK, Dv, Dv, Dv, Dv, 0, 0);
        rmsnorm_h<<<NTOK, 256>>>(p_seq, Dv, n2w + l * Dv, p_xn, 0);
        gemm_h<<<gF, 256, GEMM_SMEMH>>>(p_xn, f1, ffb1 + l * Fv, nullptr,
                                        nullptr, p_ff, NTOK, Fv, Dv, Dv, Fv, 1, 1);
        gemm_h<<<gP, 256, GEMM_SMEMH>>>(p_ff, f2, ffb2 + l * Dv, p_seq,
                                        p_seq, nullptr, NTOK, Dv, Fv, Fv, Dv, 0, 0);
    }

    // new_deter = rmsnorm(seq[:, -1] + deter, fnw)  -> out[0 : B*D)
    rmsnorm_f<<<Bv, 256>>>(p_seq + (size_t)MEMv * Dv, Sv * Dv, deter, fnw, out);
    // new_mem = seq[:, 1:17]  -> out[B*D : ]
    mem_out_k<<<(Bv * MEMv * Dv / 4 + 255) / 256, 256>>>(p_seq, out + (size_t)Bv * Dv);
}